// round 9
// baseline (speedup 1.0000x reference)
#include <cuda_runtime.h>
#include <cuda_bf16.h>

#define MAXM   512       // absolute per-class capacity (fallback path)
#define MAXB   256       // fast-path capacity (bitmap rows); actual m ~51
#define NCLS   80
#define TPB    256

__device__ float g_maxc;   // written by k_pre block 0, read by k_nms

// ---------------- kernel 1: max-reduce (block 0) + pred decode ------------
__global__ void __launch_bounds__(TPB) k_pre(const float* __restrict__ boxes,
                                             const float* __restrict__ loc,
                                             const float* __restrict__ deltas,
                                             const int*   __restrict__ stridep,
                                             float* __restrict__ out,
                                             int N, int L) {
    const int tid = threadIdx.x;

    if (blockIdx.x == 0) {
        // global coordinate max, batched loads (high MLP), one write
        __shared__ float swmax[TPB / 32];
        const float4* b4 = (const float4*)boxes;
        float mx = -3.4e38f;
        #pragma unroll 16
        for (int i = tid; i < N; i += TPB) {
            float4 v = b4[i];
            mx = fmaxf(fmaxf(fmaxf(v.x, v.y), fmaxf(v.z, v.w)), mx);
        }
        #pragma unroll
        for (int o = 16; o; o >>= 1) mx = fmaxf(mx, __shfl_xor_sync(0xffffffffu, mx, o));
        if ((tid & 31) == 0) swmax[tid >> 5] = mx;
        __syncthreads();
        if (tid == 0) {
            #pragma unroll
            for (int w = 1; w < TPB / 32; w++) mx = fmaxf(mx, swmax[w]);
            mx = fmaxf(mx, swmax[0]);
            g_maxc = mx;
        }
        return;
    }

    // pred decode + zero the keep region (covers [0,N) since L >= N)
    int i = (blockIdx.x - 1) * TPB + tid;
    if (i < N) out[i] = 0.0f;
    if (i >= L) return;
    float s = (float)stridep[0];
    float4 d = ((const float4*)deltas)[i];
    float2 p = ((const float2*)loc)[i];
    float* o = out + N + 5 * i;
    o[0] = p.x - fmaxf(d.x, 0.0f) * s;
    o[1] = p.y - fmaxf(d.y, 0.0f) * s;
    o[2] = p.x + fmaxf(d.z, 0.0f) * s;
    o[3] = p.y + fmaxf(d.w, 0.0f) * s;
    float lrmin = fminf(d.x, d.z), tbmin = fminf(d.y, d.w);
    float lrmax = fmaxf(d.x, d.z), tbmax = fmaxf(d.y, d.w);
    float cent = sqrtf((lrmin * tbmin) / (lrmax * tbmax));
    if (d.x == -1.0f && d.y == -1.0f && d.z == -1.0f && d.w == -1.0f) cent = -1.0f;
    o[4] = cent;
}

// ---------------- kernel 2: per-class NMS, one CTA per class --------------
__global__ void __launch_bounds__(TPB) k_nms(const float* __restrict__ boxes,
                                             const float* __restrict__ scores,
                                             const int*   __restrict__ cls,
                                             float* __restrict__ out, int N) {
    __shared__ float4 sbox[MAXM];      // gathered RAW coords
    __shared__ float  sscore[MAXM];
    __shared__ int    sidx[MAXM];
    __shared__ float4 sbox2[MAXM];     // sorted, OFFSET coords
    __shared__ float  sarea2[MAXM];
    __shared__ int    sidx2[MAXM];
    __shared__ int    ssupp[MAXM];     // fallback only
    __shared__ __align__(16) unsigned int srow[MAXB][8];
    __shared__ int    scnt;

    const int tid  = threadIdx.x;
    const int c    = blockIdx.x;
    const int lane = tid & 31;
    const int wid  = tid >> 5;
    const float4* b4 = (const float4*)boxes;

    const float off = (float)c * (g_maxc + 1.0f);   // one global load (prev kernel wrote it)

    if (tid == 0) scnt = 0;
    __syncthreads();

    // ---- gather members of this class (unroll-hinted int4 loads) ----
    const int4* cls4 = (const int4*)cls;
    const int nq = N >> 2;
    #pragma unroll 4
    for (int q = tid; q < nq; q += TPB) {
        int4 cv = cls4[q];
        int base = q * 4;
        #pragma unroll
        for (int u = 0; u < 4; u++) {
            int ci = (u == 0) ? cv.x : (u == 1) ? cv.y : (u == 2) ? cv.z : cv.w;
            int i = base + u;
            if (ci == c) {
                int s = atomicAdd(&scnt, 1);
                if (s < MAXM) {
                    sbox[s]   = b4[i];
                    sscore[s] = scores[i];
                    sidx[s]   = i;
                }
            }
        }
    }
    __syncthreads();
    int m = min(scnt, MAXM);
    if (m == 0) return;

    // ---- block-wide stable counting sort by (score desc, idx asc);
    //      offset + area applied in the scatter (matches ref op order) ----
    for (int k = tid; k < m; k += TPB) {
        float sk = sscore[k];
        int   ik = sidx[k];
        int   r  = 0;
        #pragma unroll 4
        for (int j = 0; j < m; j++) {
            float sj = sscore[j];
            r += (sj > sk) || (sj == sk && sidx[j] < ik);
        }
        float4 raw = sbox[k];
        float x1 = raw.x + off, y1 = raw.y + off;
        float x2 = raw.z + off, y2 = raw.w + off;
        sbox2[r]  = make_float4(x1, y1, x2, y2);
        sarea2[r] = (x2 - x1) * (y2 - y1);
        sidx2[r]  = ik;
    }
    __syncthreads();

    if (m <= MAXB) {
        // ---- m x m suppression bitmap (all 8 warps, ballot) ----
        const int nchunk = (m + 31) >> 5;
        for (int r = wid; r < m; r += TPB / 32) {
            float4 a  = sbox2[r];
            float  aa = sarea2[r];
            for (int ch = 0; ch < nchunk; ch++) {
                int j = (ch << 5) + lane;
                bool sup = false;
                if (j < m && j != r) {
                    float4 b = sbox2[j];
                    float xi = fminf(a.z, b.z) - fmaxf(a.x, b.x);
                    float yi = fminf(a.w, b.w) - fmaxf(a.y, b.y);
                    float inter = fmaxf(xi, 0.0f) * fmaxf(yi, 0.0f);
                    float iou = inter / (aa + sarea2[j] - inter);
                    sup = iou > 0.5f;
                }
                unsigned bm = __ballot_sync(0xffffffffu, sup);
                if (lane == 0) srow[r][ch] = bm;
            }
            if (lane == 0)
                for (int ch = nchunk; ch < 8; ch++) srow[r][ch] = 0u;
        }
        __syncthreads();
        if (wid != 0) return;

        // ---- scalar bit-scan, warp 0, software-pipelined row prefetch ----
        typedef unsigned long long u64;
        u64 m0 = 0, m1 = 0, m2 = 0, m3 = 0;
        const u64* rp = (const u64*)srow[0];
        u64 r0 = rp[0], r1 = rp[1], r2 = rp[2], r3 = rp[3];
        for (int i = 0; i < m; i++) {
            u64 n0 = 0, n1 = 0, n2 = 0, n3 = 0;
            if (i + 1 < m) {
                const u64* np = (const u64*)srow[i + 1];
                n0 = np[0]; n1 = np[1]; n2 = np[2]; n3 = np[3];
            }
            int w = i >> 6;
            u64 bit = 1ULL << (i & 63);
            u64 mw = (w == 0) ? m0 : (w == 1) ? m1 : (w == 2) ? m2 : m3;
            if (!(mw & bit)) {
                if (lane == 0) out[sidx2[i]] = 1.0f;
                m0 |= r0; m1 |= r1; m2 |= r2; m3 |= r3;
            }
            r0 = n0; r1 = n1; r2 = n2; r3 = n3;
        }
        return;
    }

    // ---- fallback (m > MAXB, statistically unreachable) ----
    if (wid != 0) return;
    for (int k = lane; k < m; k += 32) ssupp[k] = 0;
    __syncwarp();
    for (int i = 0; i < m; i++) {
        if (ssupp[i]) continue;
        if (lane == 0) out[sidx2[i]] = 1.0f;
        float4 a  = sbox2[i];
        float  aa = sarea2[i];
        for (int j = i + 1 + lane; j < m; j += 32) {
            if (!ssupp[j]) {
                float4 b = sbox2[j];
                float xi = fminf(a.z, b.z) - fmaxf(a.x, b.x);
                float yi = fminf(a.w, b.w) - fmaxf(a.y, b.y);
                float inter = fmaxf(xi, 0.0f) * fmaxf(yi, 0.0f);
                float iou = inter / (aa + sarea2[j] - inter);
                if (iou > 0.5f) ssupp[j] = 1;
            }
        }
        __syncwarp();
    }
}

// ---------------- launch --------------------------------------------------
extern "C" void kernel_launch(void* const* d_in, const int* in_sizes, int n_in,
                              void* d_out, int out_size) {
    const float* boxes   = (const float*)d_in[0];
    const float* scores  = (const float*)d_in[1];
    const int*   cls     = (const int*)d_in[2];
    const float* loc     = (const float*)d_in[3];
    const float* deltas  = (const float*)d_in[4];
    const int*   stridep = (const int*)d_in[5];
    int N = in_sizes[1];        // 4096 boxes
    int L = in_sizes[4] / 4;    // 16384 locations
    float* out = (float*)d_out;

    int pred_blocks = (L + TPB - 1) / TPB;
    k_pre<<<1 + pred_blocks, TPB>>>(boxes, loc, deltas, stridep, out, N, L);
    k_nms<<<NCLS, TPB>>>(boxes, scores, cls, out, N);
}

// round 10
// speedup vs baseline: 1.1860x; 1.1860x over previous
#include <cuda_runtime.h>
#include <cuda_bf16.h>

#define MAXM   512       // absolute per-class capacity (fallback path)
#define MAXB   256       // fast-path capacity (bitmap rows); actual m ~51
#define NCLS   80
#define TPB    256

__global__ void __launch_bounds__(TPB) k_fused(const float* __restrict__ boxes,
                                               const float* __restrict__ scores,
                                               const int*   __restrict__ cls,
                                               const float* __restrict__ loc,
                                               const float* __restrict__ deltas,
                                               const int*   __restrict__ stridep,
                                               float* __restrict__ out,
                                               int N, int L) {
    const int tid = threadIdx.x;

    if (blockIdx.x >= NCLS) {
        // ---------------- pred decode + centerness ----------------
        int i = (blockIdx.x - NCLS) * TPB + tid;
        if (i >= L) return;
        float s = (float)stridep[0];
        float4 d = ((const float4*)deltas)[i];
        float2 p = ((const float2*)loc)[i];
        float* o = out + N + 5 * i;
        o[0] = p.x - fmaxf(d.x, 0.0f) * s;
        o[1] = p.y - fmaxf(d.y, 0.0f) * s;
        o[2] = p.x + fmaxf(d.z, 0.0f) * s;
        o[3] = p.y + fmaxf(d.w, 0.0f) * s;
        float lrmin = fminf(d.x, d.z), tbmin = fminf(d.y, d.w);
        float lrmax = fmaxf(d.x, d.z), tbmax = fmaxf(d.y, d.w);
        float cent = sqrtf((lrmin * tbmin) / (lrmax * tbmax));
        if (d.x == -1.0f && d.y == -1.0f && d.z == -1.0f && d.w == -1.0f) cent = -1.0f;
        o[4] = cent;
        return;
    }

    // ---------------- per-class NMS ----------------
    __shared__ float4 sbox[MAXM];      // gathered RAW coords
    __shared__ float  sscore[MAXM];
    __shared__ int    sidx[MAXM];
    __shared__ float4 sbox2[MAXM];     // sorted, OFFSET coords
    __shared__ float  sarea2[MAXM];
    __shared__ int    sidx2[MAXM];
    __shared__ int    ssupp[MAXM];     // fallback only
    __shared__ __align__(16) unsigned int srow[MAXB][8];  // 256-bit rows
    __shared__ int    scnt;
    __shared__ float  swmax[TPB / 32];

    const int c    = blockIdx.x;
    const int lane = tid & 31;
    const int wid  = tid >> 5;
    const float4* b4 = (const float4*)boxes;

    if (tid == 0) scnt = 0;
    // zero srow while waiting (no dependency on loads)
    {
        uint2* sz = (uint2*)srow;                 // MAXB*8 u32 = MAXB*4 uint2
        #pragma unroll
        for (int q = tid; q < MAXB * 4; q += TPB) sz[q] = make_uint2(0u, 0u);
    }
    __syncthreads();

    // ---- ONE load window: max-reduce loads + gather (raw) loads ----
    float mx = -3.4e38f;
    #pragma unroll 4
    for (int i = tid; i < N; i += TPB) {
        float4 v = b4[i];
        mx = fmaxf(fmaxf(fmaxf(v.x, v.y), fmaxf(v.z, v.w)), mx);
    }
    const int4* cls4 = (const int4*)cls;
    #pragma unroll 4
    for (int q = tid; q < N / 4; q += TPB) {
        int4 cv = cls4[q];
        int base = q * 4;
        #pragma unroll
        for (int u = 0; u < 4; u++) {
            int ci = (u == 0) ? cv.x : (u == 1) ? cv.y : (u == 2) ? cv.z : cv.w;
            int i = base + u;
            if (ci == c) {
                out[i] = 0.0f;                 // zero keep slot (unique owner CTA)
                int s = atomicAdd(&scnt, 1);
                if (s < MAXM) {
                    sbox[s]   = b4[i];
                    sscore[s] = scores[i];
                    sidx[s]   = i;
                }
            }
        }
    }
    #pragma unroll
    for (int o = 16; o; o >>= 1) mx = fmaxf(mx, __shfl_xor_sync(0xffffffffu, mx, o));
    if (lane == 0) swmax[wid] = mx;
    __syncthreads();                           // covers gather smem + swmax
    mx = swmax[0];
    #pragma unroll
    for (int w = 1; w < TPB / 32; w++) mx = fmaxf(mx, swmax[w]);
    const float off = (float)c * (mx + 1.0f);

    int m = min(scnt, MAXM);
    if (m == 0) return;

    // ---- block-wide stable counting sort by (score desc, idx asc);
    //      offset + area applied in the scatter (matches ref op order) ----
    for (int k = tid; k < m; k += TPB) {
        float sk = sscore[k];
        int   ik = sidx[k];
        int   r  = 0;
        #pragma unroll 4
        for (int j = 0; j < m; j++) {
            float sj = sscore[j];
            r += (sj > sk) || (sj == sk && sidx[j] < ik);
        }
        float4 raw = sbox[k];
        float x1 = raw.x + off, y1 = raw.y + off;
        float x2 = raw.z + off, y2 = raw.w + off;
        sbox2[r]  = make_float4(x1, y1, x2, y2);
        sarea2[r] = (x2 - x1) * (y2 - y1);
        sidx2[r]  = ik;
    }
    __syncthreads();

    if (m <= MAXB) {
        // ---- upper-triangle suppression bitmap, division-free ----
        // Only bits j > r are ever consumed by the scan; suppress test
        // inter > 0.5*union == (inter/union > 0.5) in exact arithmetic.
        const int nchunk = (m + 31) >> 5;
        for (int r = wid; r < m; r += TPB / 32) {
            float4 a  = sbox2[r];
            float  aa = sarea2[r];
            for (int ch = r >> 5; ch < nchunk; ch++) {
                int j = (ch << 5) + lane;
                bool sup = false;
                if (j > r && j < m) {
                    float4 b = sbox2[j];
                    float xi = fminf(a.z, b.z) - fmaxf(a.x, b.x);
                    float yi = fminf(a.w, b.w) - fmaxf(a.y, b.y);
                    float inter = fmaxf(xi, 0.0f) * fmaxf(yi, 0.0f);
                    sup = inter > 0.5f * (aa + sarea2[j] - inter);
                }
                unsigned bm = __ballot_sync(0xffffffffu, sup);
                if (lane == 0) srow[r][ch] = bm;
            }
        }
        __syncthreads();
        if (wid != 0) return;

        // ---- scalar bit-scan, warp 0, software-pipelined row prefetch ----
        typedef unsigned long long u64;
        u64 m0 = 0, m1 = 0, m2 = 0, m3 = 0;
        const u64* rp = (const u64*)srow[0];
        u64 r0 = rp[0], r1 = rp[1], r2 = rp[2], r3 = rp[3];
        for (int i = 0; i < m; i++) {
            u64 n0 = 0, n1 = 0, n2 = 0, n3 = 0;
            if (i + 1 < m) {
                const u64* np = (const u64*)srow[i + 1];
                n0 = np[0]; n1 = np[1]; n2 = np[2]; n3 = np[3];
            }
            int w = i >> 6;
            u64 bit = 1ULL << (i & 63);
            u64 mw = (w == 0) ? m0 : (w == 1) ? m1 : (w == 2) ? m2 : m3;
            if (!(mw & bit)) {
                if (lane == 0) out[sidx2[i]] = 1.0f;
                m0 |= r0; m1 |= r1; m2 |= r2; m3 |= r3;
            }
            r0 = n0; r1 = n1; r2 = n2; r3 = n3;
        }
        return;
    }

    // ---- fallback (m > MAXB, statistically unreachable) ----
    if (wid != 0) return;
    for (int k = lane; k < m; k += 32) ssupp[k] = 0;
    __syncwarp();
    for (int i = 0; i < m; i++) {
        if (ssupp[i]) continue;
        if (lane == 0) out[sidx2[i]] = 1.0f;
        float4 a  = sbox2[i];
        float  aa = sarea2[i];
        for (int j = i + 1 + lane; j < m; j += 32) {
            if (!ssupp[j]) {
                float4 b = sbox2[j];
                float xi = fminf(a.z, b.z) - fmaxf(a.x, b.x);
                float yi = fminf(a.w, b.w) - fmaxf(a.y, b.y);
                float inter = fmaxf(xi, 0.0f) * fmaxf(yi, 0.0f);
                float iou = inter / (aa + sarea2[j] - inter);
                if (iou > 0.5f) ssupp[j] = 1;
            }
        }
        __syncwarp();
    }
}

// ---------------- launch --------------------------------------------------
extern "C" void kernel_launch(void* const* d_in, const int* in_sizes, int n_in,
                              void* d_out, int out_size) {
    const float* boxes   = (const float*)d_in[0];
    const float* scores  = (const float*)d_in[1];
    const int*   cls     = (const int*)d_in[2];
    const float* loc     = (const float*)d_in[3];
    const float* deltas  = (const float*)d_in[4];
    const int*   stridep = (const int*)d_in[5];
    int N = in_sizes[1];        // 4096 boxes
    int L = in_sizes[4] / 4;    // 16384 locations
    float* out = (float*)d_out;

    int pred_blocks = (L + TPB - 1) / TPB;
    k_fused<<<NCLS + pred_blocks, TPB>>>(boxes, scores, cls, loc, deltas,
                                         stridep, out, N, L);
}

// round 11
// speedup vs baseline: 1.3142x; 1.1081x over previous
#include <cuda_runtime.h>
#include <cuda_bf16.h>

#define MAXM   512       // absolute per-class capacity (fallback path)
#define MAXB   256       // fast-path capacity (bitmap rows); actual m ~51
#define NCLS   80
#define TPB    256

__global__ void __launch_bounds__(TPB) k_fused(const float* __restrict__ boxes,
                                               const float* __restrict__ scores,
                                               const int*   __restrict__ cls,
                                               const float* __restrict__ loc,
                                               const float* __restrict__ deltas,
                                               const int*   __restrict__ stridep,
                                               float* __restrict__ out,
                                               int N, int L) {
    const int tid = threadIdx.x;

    if (blockIdx.x >= NCLS) {
        // ---------------- pred decode + centerness ----------------
        int i = (blockIdx.x - NCLS) * TPB + tid;
        if (i >= L) return;
        float s = (float)stridep[0];
        float4 d = ((const float4*)deltas)[i];
        float2 p = ((const float2*)loc)[i];
        float* o = out + N + 5 * i;
        o[0] = p.x - fmaxf(d.x, 0.0f) * s;
        o[1] = p.y - fmaxf(d.y, 0.0f) * s;
        o[2] = p.x + fmaxf(d.z, 0.0f) * s;
        o[3] = p.y + fmaxf(d.w, 0.0f) * s;
        float lrmin = fminf(d.x, d.z), tbmin = fminf(d.y, d.w);
        float lrmax = fmaxf(d.x, d.z), tbmax = fmaxf(d.y, d.w);
        float cent = sqrtf((lrmin * tbmin) / (lrmax * tbmax));
        if (d.x == -1.0f && d.y == -1.0f && d.z == -1.0f && d.w == -1.0f) cent = -1.0f;
        o[4] = cent;
        return;
    }

    // ---------------- per-class NMS ----------------
    __shared__ float4 sbox[MAXM];      // gathered RAW coords
    __shared__ float  sscore[MAXM];
    __shared__ int    sidx[MAXM];
    __shared__ float4 sbox2[MAXM];     // sorted, OFFSET coords
    __shared__ float  sarea2[MAXM];
    __shared__ int    sidx2[MAXM];
    __shared__ int    ssupp[MAXM];     // fallback only
    __shared__ __align__(16) unsigned int srow[MAXB][8];  // 256-bit rows
    __shared__ int    scnt;
    __shared__ float  swmax[TPB / 32];

    const int c    = blockIdx.x;
    const int lane = tid & 31;
    const int wid  = tid >> 5;
    const float4* b4 = (const float4*)boxes;
    const int4*  cls4 = (const int4*)cls;

    if (tid == 0) scnt = 0;
    __syncthreads();

    float mx = -3.4e38f;

    if (N == 16 * TPB) {
        // ---- fast path: batch ALL streaming loads into one MLP window ----
        int4 cv[4];
        #pragma unroll
        for (int t = 0; t < 4; t++) cv[t] = cls4[tid + t * TPB];
        float4 v[8];
        #pragma unroll
        for (int t = 0; t < 8; t++) v[t] = b4[tid + t * TPB];
        #pragma unroll
        for (int t = 0; t < 8; t++)
            mx = fmaxf(mx, fmaxf(fmaxf(v[t].x, v[t].y), fmaxf(v[t].z, v[t].w)));
        #pragma unroll
        for (int t = 0; t < 8; t++) v[t] = b4[tid + (8 + t) * TPB];
        #pragma unroll
        for (int t = 0; t < 8; t++)
            mx = fmaxf(mx, fmaxf(fmaxf(v[t].x, v[t].y), fmaxf(v[t].z, v[t].w)));

        // ---- gather: warp-aggregated slot allocation (1 atomic/warp/group) ----
        #pragma unroll
        for (int t = 0; t < 4; t++) {
            int base_i = (tid + t * TPB) * 4;
            #pragma unroll
            for (int u = 0; u < 4; u++) {
                int ci = (u == 0) ? cv[t].x : (u == 1) ? cv[t].y
                       : (u == 2) ? cv[t].z : cv[t].w;
                bool match = (ci == c);
                unsigned bal = __ballot_sync(0xffffffffu, match);
                if (bal) {                                 // warp-uniform
                    int wbase;
                    if (lane == 0) wbase = atomicAdd(&scnt, __popc(bal));
                    wbase = __shfl_sync(0xffffffffu, wbase, 0);
                    if (match) {
                        int s = wbase + __popc(bal & ((1u << lane) - 1u));
                        int i = base_i + u;
                        out[i] = 0.0f;                     // zero keep slot
                        if (s < MAXM) {
                            sbox[s]   = b4[i];
                            sscore[s] = scores[i];
                            sidx[s]   = i;
                        }
                    }
                }
            }
        }
    } else {
        // ---- generic path (unused for this shape) ----
        for (int i = tid; i < N; i += TPB) {
            float4 v = b4[i];
            mx = fmaxf(mx, fmaxf(fmaxf(v.x, v.y), fmaxf(v.z, v.w)));
        }
        for (int q = tid; q < (N >> 2); q += TPB) {
            int4 cv = cls4[q];
            int base = q * 4;
            #pragma unroll
            for (int u = 0; u < 4; u++) {
                int ci = (u == 0) ? cv.x : (u == 1) ? cv.y : (u == 2) ? cv.z : cv.w;
                int i = base + u;
                if (i < N && ci == c) {
                    out[i] = 0.0f;
                    int s = atomicAdd(&scnt, 1);
                    if (s < MAXM) {
                        sbox[s]   = b4[i];
                        sscore[s] = scores[i];
                        sidx[s]   = i;
                    }
                }
            }
        }
    }

    #pragma unroll
    for (int o = 16; o; o >>= 1) mx = fmaxf(mx, __shfl_xor_sync(0xffffffffu, mx, o));
    if (lane == 0) swmax[wid] = mx;
    __syncthreads();                           // covers gather smem + swmax
    mx = swmax[0];
    #pragma unroll
    for (int w = 1; w < TPB / 32; w++) mx = fmaxf(mx, swmax[w]);
    const float off = (float)c * (mx + 1.0f);

    int m = min(scnt, MAXM);
    if (m == 0) return;

    // ---- block-wide stable counting sort by (score desc, idx asc);
    //      offset + area applied in the scatter (matches ref op order) ----
    for (int k = tid; k < m; k += TPB) {
        float sk = sscore[k];
        int   ik = sidx[k];
        int   r  = 0;
        #pragma unroll 4
        for (int j = 0; j < m; j++) {
            float sj = sscore[j];
            r += (sj > sk) || (sj == sk && sidx[j] < ik);
        }
        float4 raw = sbox[k];
        float x1 = raw.x + off, y1 = raw.y + off;
        float x2 = raw.z + off, y2 = raw.w + off;
        sbox2[r]  = make_float4(x1, y1, x2, y2);
        sarea2[r] = (x2 - x1) * (y2 - y1);
        sidx2[r]  = ik;
    }
    __syncthreads();

    if (m <= MAXB) {
        // ---- upper-triangle suppression bitmap, division-free.
        //      Low chunks (below diagonal) zeroed here; chunks >= nchunk stay
        //      garbage — they only OR into mask bits >= m, which are never
        //      tested by the scan. ----
        const int nchunk = (m + 31) >> 5;
        for (int r = wid; r < m; r += TPB / 32) {
            int dch = r >> 5;
            if (lane < dch) srow[r][lane] = 0u;            // dch <= 7
            float4 a  = sbox2[r];
            float  aa = sarea2[r];
            for (int ch = dch; ch < nchunk; ch++) {
                int j = (ch << 5) + lane;
                bool sup = false;
                if (j > r && j < m) {
                    float4 b = sbox2[j];
                    float xi = fminf(a.z, b.z) - fmaxf(a.x, b.x);
                    float yi = fminf(a.w, b.w) - fmaxf(a.y, b.y);
                    float inter = fmaxf(xi, 0.0f) * fmaxf(yi, 0.0f);
                    sup = inter > 0.5f * (aa + sarea2[j] - inter);
                }
                unsigned bm = __ballot_sync(0xffffffffu, sup);
                if (lane == 0) srow[r][ch] = bm;
            }
        }
        __syncthreads();
        if (wid != 0) return;

        // ---- scalar bit-scan, warp 0, software-pipelined row prefetch ----
        typedef unsigned long long u64;
        u64 m0 = 0, m1 = 0, m2 = 0, m3 = 0;
        const u64* rp = (const u64*)srow[0];
        u64 r0 = rp[0], r1 = rp[1], r2 = rp[2], r3 = rp[3];
        for (int i = 0; i < m; i++) {
            u64 n0 = 0, n1 = 0, n2 = 0, n3 = 0;
            if (i + 1 < m) {
                const u64* np = (const u64*)srow[i + 1];
                n0 = np[0]; n1 = np[1]; n2 = np[2]; n3 = np[3];
            }
            int w = i >> 6;
            u64 bit = 1ULL << (i & 63);
            u64 mw = (w == 0) ? m0 : (w == 1) ? m1 : (w == 2) ? m2 : m3;
            if (!(mw & bit)) {
                if (lane == 0) out[sidx2[i]] = 1.0f;
                m0 |= r0; m1 |= r1; m2 |= r2; m3 |= r3;
            }
            r0 = n0; r1 = n1; r2 = n2; r3 = n3;
        }
        return;
    }

    // ---- fallback (m > MAXB, statistically unreachable) ----
    if (wid != 0) return;
    for (int k = lane; k < m; k += 32) ssupp[k] = 0;
    __syncwarp();
    for (int i = 0; i < m; i++) {
        if (ssupp[i]) continue;
        if (lane == 0) out[sidx2[i]] = 1.0f;
        float4 a  = sbox2[i];
        float  aa = sarea2[i];
        for (int j = i + 1 + lane; j < m; j += 32) {
            if (!ssupp[j]) {
                float4 b = sbox2[j];
                float xi = fminf(a.z, b.z) - fmaxf(a.x, b.x);
                float yi = fminf(a.w, b.w) - fmaxf(a.y, b.y);
                float inter = fmaxf(xi, 0.0f) * fmaxf(yi, 0.0f);
                float iou = inter / (aa + sarea2[j] - inter);
                if (iou > 0.5f) ssupp[j] = 1;
            }
        }
        __syncwarp();
    }
}

// ---------------- launch --------------------------------------------------
extern "C" void kernel_launch(void* const* d_in, const int* in_sizes, int n_in,
                              void* d_out, int out_size) {
    const float* boxes   = (const float*)d_in[0];
    const float* scores  = (const float*)d_in[1];
    const int*   cls     = (const int*)d_in[2];
    const float* loc     = (const float*)d_in[3];
    const float* deltas  = (const float*)d_in[4];
    const int*   stridep = (const int*)d_in[5];
    int N = in_sizes[1];        // 4096 boxes
    int L = in_sizes[4] / 4;    // 16384 locations
    float* out = (float*)d_out;

    int pred_blocks = (L + TPB - 1) / TPB;
    k_fused<<<NCLS + pred_blocks, TPB>>>(boxes, scores, cls, loc, deltas,
                                         stridep, out, N, L);
}